// round 2
// baseline (speedup 1.0000x reference)
#include <cuda_runtime.h>
#include <math.h>

#define NQ      14
#define DIM     16384
#define NT      10
#define BATCH   2048
#define NTHR    1024
#define EPT     16          // elements per thread: DIM / NTHR
#define ZZN     8192        // distinct Gray masks over 13 couplings
#define DYN_SMEM ((DIM + ZZN) * (int)sizeof(float2))   // 196608 bytes

// 42 output constants: for i=0..13 (q = 13-i):
//   g_const[3i]   = 2*Re(C_q),  g_const[3i+1] = 2*Im(C_q),  g_const[3i+2] = Z_q
__device__ float g_const[48];

__global__ __launch_bounds__(NTHR, 1)
void evolve_kernel(const float* __restrict__ J, const float* __restrict__ g)
{
    extern __shared__ float2 dyn[];
    float2* buf = dyn;          // [EPT][NTHR]: buf[e*NTHR + tid]  (exchange/state)
    float2* zz  = dyn + DIM;    // ZZN entries, bit-permuted for conflict-free reads

    __shared__ float2 rxc[16];
    __shared__ float  Jsh[16];
    __shared__ float  warpacc[42 * 32];

    const int tid  = threadIdx.x;
    const int lane = tid & 31;
    const int wrp  = tid >> 5;
    const float dt = 1.0f / (float)NT;

    // Stage small params
    if (tid < NQ) {
        float h = 0.5f * g[tid] * dt;
        rxc[tid] = make_float2(cosf(h), sinf(h));
    }
    if (tid < NQ - 1) Jsh[tid] = J[tid];
    __syncthreads();

    // Precompute ZZ diagonal factors: for Gray mask m (13 bits),
    // D = sum_i J_i * (1 - 2*m_i), factor = exp(-0.5i*dt*D).
    // Stored at permuted index ((m&7)<<10)|(m>>3) so runtime reads are conflict-free.
    for (int m = tid; m < ZZN; m += NTHR) {
        float D = 0.f;
        #pragma unroll
        for (int i = 0; i < NQ - 1; i++) {
            float Ji = Jsh[i];
            D += ((m >> i) & 1) ? -Ji : Ji;
        }
        float ang = -0.5f * dt * D;
        int idx = ((m & 7) << 10) | (m >> 3);
        zz[idx] = make_float2(cosf(ang), sinf(ang));
    }
    __syncthreads();

    // Initial state: H^{x14} |0...0> = uniform amplitude 1/128 (all +).
    float2 v[EPT];
    #pragma unroll
    for (int e = 0; e < EPT; e++) v[e] = make_float2(0.0078125f, 0.f);

    // Gray base for this thread's elements: m(k) = (k ^ (k>>1)) & 8191, k = tid*16 + e
    const int base = (((tid << 4) ^ (tid << 3)) & (ZZN - 1));

    for (int t = 0; t < NT; t++) {
        // ---- ZZ layer (diagonal, exact product of all 13 ZZ gates) ----
        #pragma unroll
        for (int e = 0; e < EPT; e++) {
            int m = base ^ (e ^ (e >> 1));          // (e^(e>>1)) is a compile-time const
            float2 f = zz[((m & 7) << 10) | (m >> 3)];
            float2 a = v[e];
            v[e] = make_float2(a.x * f.x - a.y * f.y, a.x * f.y + a.y * f.x);
        }
        // ---- RX on qubits 0..3 (thread-local butterflies) ----
        #pragma unroll
        for (int q = 0; q < 4; q++) {
            float2 cs = rxc[q];
            float c = cs.x, s = cs.y;
            #pragma unroll
            for (int e = 0; e < EPT; e++) {
                if (!(e & (1 << q))) {
                    int e1 = e | (1 << q);
                    float2 a = v[e], b = v[e1];
                    // RX = [[c, -i s],[-i s, c]]
                    v[e]  = make_float2(c * a.x + s * b.y, c * a.y - s * b.x);
                    v[e1] = make_float2(c * b.x + s * a.y, c * b.y - s * a.x);
                }
            }
        }
        // ---- RX on qubits 4..8 (lane bits: warp shuffle butterflies) ----
        #pragma unroll
        for (int q = 4; q < 9; q++) {
            float2 cs = rxc[q];
            float c = cs.x, s = cs.y;
            int msk = 1 << (q - 4);
            #pragma unroll
            for (int e = 0; e < EPT; e++) {
                float ox = __shfl_xor_sync(0xffffffffu, v[e].x, msk);
                float oy = __shfl_xor_sync(0xffffffffu, v[e].y, msk);
                v[e] = make_float2(c * v[e].x + s * oy, c * v[e].y - s * ox);
            }
        }
        // ---- RX on qubits 9..13 (warp bits: shared-memory exchange) ----
        for (int q = 9; q < NQ; q++) {
            float2 cs = rxc[q];
            float c = cs.x, s = cs.y;
            #pragma unroll
            for (int e = 0; e < EPT; e++) buf[e * NTHR + tid] = v[e];
            __syncthreads();
            int pt = tid ^ (32 << (q - 9));
            #pragma unroll
            for (int e = 0; e < EPT; e++) {
                float2 o = buf[e * NTHR + pt];
                v[e] = make_float2(c * v[e].x + s * o.y, c * v[e].y - s * o.x);
            }
            __syncthreads();
        }
    }

    // ---- Constants: C_q = sum_{k: k_q=0} conj(psi[k]) psi[k+2^q],  Z_q = sum (1-2k_q)|psi[k]|^2
    #pragma unroll
    for (int e = 0; e < EPT; e++) buf[e * NTHR + tid] = v[e];   // final state for warp-bit pairs
    __syncthreads();

    float tot = 0.f;
    #pragma unroll
    for (int e = 0; e < EPT; e++) tot += v[e].x * v[e].x + v[e].y * v[e].y;

    for (int q = 0; q < NQ; q++) {
        float cr = 0.f, ci = 0.f, zv = 0.f;
        if (q < 4) {
            #pragma unroll
            for (int e = 0; e < EPT; e++) {
                float n2 = v[e].x * v[e].x + v[e].y * v[e].y;
                zv += (e & (1 << q)) ? -n2 : n2;
            }
            #pragma unroll
            for (int e = 0; e < EPT; e++) {
                if (!(e & (1 << q))) {
                    float2 a = v[e], b = v[e | (1 << q)];
                    cr += a.x * b.x + a.y * b.y;      // Re(conj(a)*b)
                    ci += a.x * b.y - a.y * b.x;      // Im(conj(a)*b)
                }
            }
        } else if (q < 9) {
            int msk = 1 << (q - 4);
            int mybit = (lane >> (q - 4)) & 1;
            #pragma unroll
            for (int e = 0; e < EPT; e++) {
                float ox = __shfl_xor_sync(0xffffffffu, v[e].x, msk);
                float oy = __shfl_xor_sync(0xffffffffu, v[e].y, msk);
                if (!mybit) {
                    cr += v[e].x * ox + v[e].y * oy;
                    ci += v[e].x * oy - v[e].y * ox;
                }
            }
            zv = mybit ? -tot : tot;
        } else {
            int pt = tid ^ (32 << (q - 9));
            int mybit = (wrp >> (q - 9)) & 1;
            #pragma unroll
            for (int e = 0; e < EPT; e++) {
                float2 o = buf[e * NTHR + pt];
                if (!mybit) {
                    cr += v[e].x * o.x + v[e].y * o.y;
                    ci += v[e].x * o.y - v[e].y * o.x;
                }
            }
            zv = mybit ? -tot : tot;
        }
        // deterministic warp reduction
        #pragma unroll
        for (int o = 16; o > 0; o >>= 1) {
            cr += __shfl_down_sync(0xffffffffu, cr, o);
            ci += __shfl_down_sync(0xffffffffu, ci, o);
            zv += __shfl_down_sync(0xffffffffu, zv, o);
        }
        if (lane == 0) {
            int i3 = 3 * (13 - q);
            warpacc[(i3 + 0) * 32 + wrp] = cr;
            warpacc[(i3 + 1) * 32 + wrp] = ci;
            warpacc[(i3 + 2) * 32 + wrp] = zv;
        }
    }
    __syncthreads();
    if (tid < 42) {
        float ssum = 0.f;
        #pragma unroll
        for (int w = 0; w < 32; w++) ssum += warpacc[tid * 32 + w];
        if ((tid % 3) != 2) ssum *= 2.f;          // outputs are 2*Re, 2*Im, Z
        g_const[tid] = ssum;
    }
}

// out[b, 3i]   = 2Re(C_q)cos(x_bq) - 2Im(C_q)sin(x_bq)
// out[b, 3i+1] = 2Re(C_q)sin(x_bq) + 2Im(C_q)cos(x_bq)
// out[b, 3i+2] = Z_q                            with q = 13 - i
__global__ __launch_bounds__(128)
void batch_kernel(const float* __restrict__ x, float* __restrict__ out)
{
    __shared__ float so[128 * 42];
    __shared__ float cst[42];
    int tid = threadIdx.x;
    if (tid < 42) cst[tid] = g_const[tid];
    __syncthreads();

    int b = blockIdx.x * 128 + tid;
    #pragma unroll
    for (int i = 0; i < NQ; i++) {
        int q = 13 - i;
        float xv = x[b * NQ + q];
        float sn, cn;
        sincosf(xv, &sn, &cn);
        float Rc = cst[3 * i], Ic = cst[3 * i + 1];
        so[tid * 42 + 3 * i + 0] = Rc * cn - Ic * sn;
        so[tid * 42 + 3 * i + 1] = Rc * sn + Ic * cn;
        so[tid * 42 + 3 * i + 2] = cst[3 * i + 2];
    }
    __syncthreads();

    // coalesced block-contiguous store
    float* ob = out + blockIdx.x * (128 * 42);
    for (int j = tid; j < 128 * 42; j += 128) ob[j] = so[j];
}

extern "C" void kernel_launch(void* const* d_in, const int* in_sizes, int n_in,
                              void* d_out, int out_size)
{
    // Identify inputs by element count (metadata order: x[2048*14], J[13], g[14])
    const float* x = nullptr;
    const float* J = nullptr;
    const float* g = nullptr;
    for (int i = 0; i < n_in; i++) {
        if (in_sizes[i] == BATCH * NQ) x = (const float*)d_in[i];
        else if (in_sizes[i] == NQ - 1) J = (const float*)d_in[i];
        else if (in_sizes[i] == NQ)     g = (const float*)d_in[i];
    }
    if (!x) x = (const float*)d_in[0];
    if (!J) J = (const float*)d_in[1];
    if (!g) g = (const float*)d_in[2];
    float* out = (float*)d_out;

    cudaFuncSetAttribute(evolve_kernel,
                         cudaFuncAttributeMaxDynamicSharedMemorySize, DYN_SMEM);

    evolve_kernel<<<1, NTHR, DYN_SMEM>>>(J, g);
    batch_kernel<<<BATCH / 128, 128>>>(x, out);
}